// round 1
// baseline (speedup 1.0000x reference)
#include <cuda_runtime.h>

#define HH 160
#define WW 160
#define BB 4
#define CC 64
#define COUT 64
#define OFFC 64
#define K2 9
#define HW (HH*WW)             // 25600
#define KDIM (CC*K2)           // 576
#define OUT_MAIN (BB*COUT*HW)  // 6553600
#define OUT_OFF  (BB*2*K2*HW)  // 1843200
#define EPSV 1e-5f
#define TP 32
#define SPITCH 33
#define SMEM_BYTES ((KDIM*SPITCH + 4*TP*K2 /*wts*/ + 4*TP*K2 /*bases*/) * 4)

__device__ float g_xh[BB*HW*CC];      // x in NHWC
__device__ float g_wt[KDIM*COUT];     // Wt[k][cout], k = c*9 + tap
__device__ float g_off[BB*2*K2*HW];   // clamped offsets, NCHW [B,18,H,W]
__device__ float g_part[COUT*16*2];   // per-channel partial (sum, sumsq)
__device__ float g_scale[COUT];
__device__ float g_shift[COUT];

// ---------------------------------------------------------------------------
// NCHW -> NHWC transpose of x.  grid (10, B*H), block (32,8)
// ---------------------------------------------------------------------------
__global__ void k_transpose(const float* __restrict__ x) {
    __shared__ float tile[32][33];
    int bh = blockIdx.y;
    int b = bh / HH, h = bh % HH;
    int tw = blockIdx.x % 5;       // 5 w-tiles of 32
    int tc = blockIdx.x / 5;       // 2 c-tiles of 32
    int w = tw * 32 + threadIdx.x;
    #pragma unroll
    for (int i = 0; i < 4; i++) {
        int cl = threadIdx.y + i * 8;
        int c = tc * 32 + cl;
        tile[cl][threadIdx.x] = x[((b*CC + c)*HH + h)*WW + w];
    }
    __syncthreads();
    #pragma unroll
    for (int i = 0; i < 4; i++) {
        int wl = threadIdx.y + i * 8;
        int ww = tw * 32 + wl;
        int c = tc * 32 + threadIdx.x;
        g_xh[((b*HH + h)*WW + ww)*CC + c] = tile[threadIdx.x][wl];
    }
}

// ---------------------------------------------------------------------------
// conv_w [cout][cin][3][3] -> Wt[k][cout], k = cin*9 + tap
// ---------------------------------------------------------------------------
__global__ void k_wreorder(const float* __restrict__ cw) {
    int i = blockIdx.x * 256 + threadIdx.x;
    if (i < KDIM * COUT) {
        int k = i >> 6, co = i & 63;
        g_wt[k * COUT + co] = cw[co * KDIM + k];
    }
}

// ---------------------------------------------------------------------------
// Offset branch: 3x3 conv(d, offset_w), clamp to [-1,1].
// grid (5, 20, B), block 256 (tile 32x8 pixels). All 18 outputs in regs.
// ---------------------------------------------------------------------------
__global__ void k_offconv(const float* __restrict__ d,
                          const float* __restrict__ ow,
                          float* __restrict__ outoff) {
    __shared__ float wsm[18 * OFFC * 9];   // 41472 B
    __shared__ float tsm[10][34];
    int tid = threadIdx.x;
    for (int i = tid; i < 18 * OFFC * 9; i += 256) wsm[i] = ow[i];
    int b = blockIdx.z;
    int h0 = blockIdx.y * 8, w0 = blockIdx.x * 32;
    int tx = tid & 31, ty = tid >> 5;
    int h = h0 + ty, w = w0 + tx;
    float acc[18];
    #pragma unroll
    for (int o = 0; o < 18; o++) acc[o] = 0.f;
    __syncthreads();
    for (int c = 0; c < OFFC; c++) {
        for (int i = tid; i < 340; i += 256) {
            int r = i / 34, cc = i % 34;
            int y = h0 + r - 1, x = w0 + cc - 1;
            float v = 0.f;
            if (y >= 0 && y < HH && x >= 0 && x < WW)
                v = d[((b*OFFC + c)*HH + y)*WW + x];
            tsm[r][cc] = v;
        }
        __syncthreads();
        float v[9];
        #pragma unroll
        for (int t = 0; t < 9; t++)
            v[t] = tsm[ty + t/3][tx + t%3];
        #pragma unroll
        for (int o = 0; o < 18; o++) {
            const float* wp = &wsm[(o*OFFC + c)*9];
            float a = acc[o];
            #pragma unroll
            for (int t = 0; t < 9; t++) a += wp[t] * v[t];
            acc[o] = a;
        }
        __syncthreads();
    }
    #pragma unroll
    for (int o = 0; o < 18; o++) {
        float val = fminf(1.f, fmaxf(-1.f, acc[o]));
        int idx = ((b*18 + o)*HH + h)*WW + w;
        g_off[idx] = val;
        if (outoff) outoff[idx] = val;
    }
}

// ---------------------------------------------------------------------------
// Main deformable conv: per 32-pixel row tile.
//  stage1: precompute 4 (base,weight) per (pixel,tap), validity folded into w
//  stage2: gather bilinear samples into S[k=c*9+tap][pixel] (pitch 33)
//  stage3: register-blocked GEMM, out[32 px][64 cout], weights from L2
// grid (5, 160, B), block 256, dynamic smem
// ---------------------------------------------------------------------------
__global__ void k_deform(float* __restrict__ out) {
    extern __shared__ float smem[];
    float* S    = smem;                       // [576][33]
    float* sWt  = S + KDIM * SPITCH;          // [4][288]
    int*   sBse = (int*)(sWt + 4 * TP * K2);  // [4][288]
    int tid = threadIdx.x;
    int b = blockIdx.z, h = blockIdx.y, w0 = blockIdx.x * TP;

    // ---- stage 1: coords ----
    for (int pr = tid; pr < TP * K2; pr += 256) {
        int p = pr / K2, tap = pr % K2;
        int w = w0 + p;
        float dy = g_off[((b*18 + 2*tap    )*HH + h)*WW + w];
        float dx = g_off[((b*18 + 2*tap + 1)*HH + h)*WW + w];
        float py = (float)h - 1.f + (float)(tap / 3) + dy;
        float px = (float)w - 1.f + (float)(tap % 3) + dx;
        float y0f = floorf(py), x0f = floorf(px);
        float fy = py - y0f, fx = px - x0f;
        int y0 = (int)y0f, x0 = (int)x0f;
        #pragma unroll
        for (int cn = 0; cn < 4; cn++) {
            int yy = y0 + (cn >> 1), xx = x0 + (cn & 1);
            float wt = ((cn >> 1) ? fy : 1.f - fy) * ((cn & 1) ? fx : 1.f - fx);
            bool valid = (yy >= 0) && (yy < HH) && (xx >= 0) && (xx < WW);
            int yc = min(max(yy, 0), HH - 1), xc = min(max(xx, 0), WW - 1);
            sWt[cn * (TP*K2) + pr]  = valid ? wt : 0.f;
            sBse[cn * (TP*K2) + pr] = ((b*HH + yc)*WW + xc) * CC;
        }
    }
    __syncthreads();

    // ---- stage 2: gather ----
    {
        int ch = tid & 63, q = tid >> 6;
        #pragma unroll 2
        for (int it = 0; it < (TP * K2) / 4; it++) {
            int pr = it * 4 + q;
            int p = pr / K2, tap = pr % K2;
            float v = sWt[pr]            * g_xh[sBse[pr] + ch]
                    + sWt[288 + pr]      * g_xh[sBse[288 + pr] + ch]
                    + sWt[576 + pr]      * g_xh[sBse[576 + pr] + ch]
                    + sWt[864 + pr]      * g_xh[sBse[864 + pr] + ch];
            S[(ch * 9 + tap) * SPITCH + p] = v;
        }
    }
    __syncthreads();

    // ---- stage 3: GEMM ----
    int p = tid & 31, cb = (tid >> 5) * 8;
    float acc[8];
    #pragma unroll
    for (int j = 0; j < 8; j++) acc[j] = 0.f;
    const float4* wt4 = (const float4*)g_wt;
    #pragma unroll 4
    for (int k = 0; k < KDIM; k++) {
        float s = S[k * SPITCH + p];
        float4 wa = wt4[(k * COUT + cb) >> 2];
        float4 wb = wt4[(k * COUT + cb + 4) >> 2];
        acc[0] += s * wa.x; acc[1] += s * wa.y;
        acc[2] += s * wa.z; acc[3] += s * wa.w;
        acc[4] += s * wb.x; acc[5] += s * wb.y;
        acc[6] += s * wb.z; acc[7] += s * wb.w;
    }
    #pragma unroll
    for (int j = 0; j < 8; j++)
        out[((b*COUT + cb + j)*HH + h)*WW + w0 + p] = acc[j];
}

// ---------------------------------------------------------------------------
// BN stats: deterministic 2-stage reduction. grid (64, 16), block 256.
// ---------------------------------------------------------------------------
__global__ void k_stats(const float* __restrict__ out) {
    int c = blockIdx.x, bi = blockIdx.y;
    float s = 0.f, sq = 0.f;
    for (int n = bi * 256 + threadIdx.x; n < BB * HW; n += gridDim.y * 256) {
        int b = n / HW, i = n - b * HW;
        float v = out[(b * COUT + c) * HW + i];
        s += v; sq += v * v;
    }
    __shared__ float rs[256], rq[256];
    rs[threadIdx.x] = s; rq[threadIdx.x] = sq;
    __syncthreads();
    for (int st = 128; st > 0; st >>= 1) {
        if (threadIdx.x < st) {
            rs[threadIdx.x] += rs[threadIdx.x + st];
            rq[threadIdx.x] += rq[threadIdx.x + st];
        }
        __syncthreads();
    }
    if (threadIdx.x == 0) {
        g_part[(c * 16 + bi) * 2]     = rs[0];
        g_part[(c * 16 + bi) * 2 + 1] = rq[0];
    }
}

__global__ void k_finalize(const float* __restrict__ gamma,
                           const float* __restrict__ beta) {
    int c = threadIdx.x;
    if (c < COUT) {
        float s = 0.f, sq = 0.f;
        for (int i = 0; i < 16; i++) {
            s  += g_part[(c * 16 + i) * 2];
            sq += g_part[(c * 16 + i) * 2 + 1];
        }
        float inv_n = 1.f / (float)(BB * HW);
        float mean = s * inv_n;
        float var  = sq * inv_n - mean * mean;
        float sc = gamma[c] * rsqrtf(var + EPSV);
        g_scale[c] = sc;
        g_shift[c] = beta[c] - mean * sc;
    }
}

__global__ void k_bnrelu(float* __restrict__ out) {
    int idx = blockIdx.x * 256 + threadIdx.x;     // float4 index
    int c = (idx / (HW / 4)) & 63;
    float sc = g_scale[c], sh = g_shift[c];
    float4 v = ((float4*)out)[idx];
    v.x = fmaxf(0.f, v.x * sc + sh);
    v.y = fmaxf(0.f, v.y * sc + sh);
    v.z = fmaxf(0.f, v.z * sc + sh);
    v.w = fmaxf(0.f, v.w * sc + sh);
    ((float4*)out)[idx] = v;
}

// ---------------------------------------------------------------------------
extern "C" void kernel_launch(void* const* d_in, const int* in_sizes, int n_in,
                              void* d_out, int out_size) {
    const float* x     = (const float*)d_in[0];
    const float* d     = (const float*)d_in[1];
    const float* ow    = (const float*)d_in[2];
    const float* cw    = (const float*)d_in[3];
    const float* gamma = (const float*)d_in[4];
    const float* beta  = (const float*)d_in[5];
    float* out = (float*)d_out;
    float* outoff = (out_size >= OUT_MAIN + OUT_OFF) ? (out + OUT_MAIN) : nullptr;

    cudaFuncSetAttribute(k_deform, cudaFuncAttributeMaxDynamicSharedMemorySize,
                         SMEM_BYTES);

    k_transpose<<<dim3(10, BB * HH, 1), dim3(32, 8)>>>(x);
    k_wreorder<<<(KDIM * COUT + 255) / 256, 256>>>(cw);
    k_offconv<<<dim3(5, 20, BB), 256>>>(d, ow, outoff);
    k_deform<<<dim3(5, HH, BB), 256, SMEM_BYTES>>>(out);
    k_stats<<<dim3(COUT, 16), 256>>>(out);
    k_finalize<<<1, 64>>>(gamma, beta);
    k_bnrelu<<<OUT_MAIN / 4 / 256, 256>>>(out);
}

// round 3
// speedup vs baseline: 2.7000x; 2.7000x over previous
#include <cuda_runtime.h>
#include <cuda_bf16.h>
#include <cstdint>

#define HH 160
#define WW 160
#define BB 4
#define CC 64
#define COUT 64
#define OFFC 64
#define K2 9
#define HW (HH*WW)             // 25600
#define OUT_MAIN (BB*COUT*HW)  // 6553600
#define OUT_OFF  (BB*2*K2*HW)  // 1843200
#define EPSV 1e-5f

// ---- warp-MMA helpers (plain PTX, works on .target sm_103) ----------------
__device__ __forceinline__ uint32_t smem_u32(const void* p) {
    uint32_t a;
    asm("{ .reg .u64 t; cvta.to.shared.u64 t, %1; cvt.u32.u64 %0, t; }"
        : "=r"(a) : "l"(p));
    return a;
}
__device__ __forceinline__ void ldsm_x4(uint32_t& r0, uint32_t& r1,
                                        uint32_t& r2, uint32_t& r3, uint32_t a) {
    asm volatile("ldmatrix.sync.aligned.m8n8.x4.shared.b16 {%0,%1,%2,%3}, [%4];"
                 : "=r"(r0), "=r"(r1), "=r"(r2), "=r"(r3) : "r"(a));
}
__device__ __forceinline__ void ldsm_x4t(uint32_t& r0, uint32_t& r1,
                                         uint32_t& r2, uint32_t& r3, uint32_t a) {
    asm volatile("ldmatrix.sync.aligned.m8n8.x4.trans.shared.b16 {%0,%1,%2,%3}, [%4];"
                 : "=r"(r0), "=r"(r1), "=r"(r2), "=r"(r3) : "r"(a));
}
__device__ __forceinline__ void mma16816(float* c, uint32_t a0, uint32_t a1,
                                         uint32_t a2, uint32_t a3,
                                         uint32_t b0, uint32_t b1) {
    asm volatile("mma.sync.aligned.m16n8k16.row.col.f32.bf16.bf16.f32 "
                 "{%0,%1,%2,%3}, {%4,%5,%6,%7}, {%8,%9}, {%0,%1,%2,%3};"
                 : "+f"(c[0]), "+f"(c[1]), "+f"(c[2]), "+f"(c[3])
                 : "r"(a0), "r"(a1), "r"(a2), "r"(a3), "r"(b0), "r"(b1));
}
__device__ __forceinline__ uint32_t sw128(uint32_t off) {
    return off ^ ((off >> 3) & 0x70);
}

// ---- global scratch -------------------------------------------------------
__device__ float g_xh[BB*HW*CC];                 // x in NHWC fp32
__device__ __nv_bfloat16 g_wbh[K2*CC*COUT];      // W hi  [tap][cin][cout]
__device__ __nv_bfloat16 g_wbl[K2*CC*COUT];      // W lo
__device__ float g_off[BB*2*K2*HW];              // clamped offsets NCHW
__device__ float g_part[COUT*16*2];
__device__ float g_scale[COUT];
__device__ float g_shift[COUT];

// ---------------------------------------------------------------------------
// NCHW -> NHWC transpose of x
// ---------------------------------------------------------------------------
__global__ void k_transpose(const float* __restrict__ x) {
    __shared__ float tile[32][33];
    int bh = blockIdx.y;
    int b = bh / HH, h = bh % HH;
    int tw = blockIdx.x % 5, tc = blockIdx.x / 5;
    int w = tw * 32 + threadIdx.x;
    #pragma unroll
    for (int i = 0; i < 4; i++) {
        int cl = threadIdx.y + i * 8;
        tile[cl][threadIdx.x] = x[((b*CC + tc*32 + cl)*HH + h)*WW + w];
    }
    __syncthreads();
    #pragma unroll
    for (int i = 0; i < 4; i++) {
        int wl = threadIdx.y + i * 8;
        g_xh[((b*HH + h)*WW + tw*32 + wl)*CC + tc*32 + threadIdx.x]
            = tile[threadIdx.x][wl];
    }
}

// ---------------------------------------------------------------------------
// Split conv_w into bf16 hi/lo, reorder to [tap][cin][cout]
// ---------------------------------------------------------------------------
__global__ void k_wsplit(const float* __restrict__ cw) {
    int i = blockIdx.x * 256 + threadIdx.x;      // K2*CC*COUT = 36864
    if (i < K2*CC*COUT) {
        int tap = i / (CC*COUT), ci = (i / COUT) % CC, co = i % COUT;
        float w = cw[(co*CC + ci)*K2 + tap];
        __nv_bfloat16 h = __float2bfloat16(w);
        float lo = w - __bfloat162float(h);
        g_wbh[i] = h;
        g_wbl[i] = __float2bfloat16(lo);
    }
}

// ---------------------------------------------------------------------------
// Offset branch: 3x3 conv(d, offset_w), clamp to [-1,1]
// ---------------------------------------------------------------------------
__global__ void k_offconv(const float* __restrict__ d,
                          const float* __restrict__ ow,
                          float* __restrict__ outoff) {
    __shared__ float wsm[18 * OFFC * 9];
    __shared__ float tsm[10][34];
    int tid = threadIdx.x;
    for (int i = tid; i < 18 * OFFC * 9; i += 256) wsm[i] = ow[i];
    int b = blockIdx.z;
    int h0 = blockIdx.y * 8, w0 = blockIdx.x * 32;
    int tx = tid & 31, ty = tid >> 5;
    int h = h0 + ty, w = w0 + tx;
    float acc[18];
    #pragma unroll
    for (int o = 0; o < 18; o++) acc[o] = 0.f;
    __syncthreads();
    for (int c = 0; c < OFFC; c++) {
        for (int i = tid; i < 340; i += 256) {
            int r = i / 34, cc = i % 34;
            int y = h0 + r - 1, x = w0 + cc - 1;
            float v = 0.f;
            if (y >= 0 && y < HH && x >= 0 && x < WW)
                v = d[((b*OFFC + c)*HH + y)*WW + x];
            tsm[r][cc] = v;
        }
        __syncthreads();
        float v[9];
        #pragma unroll
        for (int t = 0; t < 9; t++) v[t] = tsm[ty + t/3][tx + t%3];
        #pragma unroll
        for (int o = 0; o < 18; o++) {
            const float* wp = &wsm[(o*OFFC + c)*9];
            float a = acc[o];
            #pragma unroll
            for (int t = 0; t < 9; t++) a += wp[t] * v[t];
            acc[o] = a;
        }
        __syncthreads();
    }
    #pragma unroll
    for (int o = 0; o < 18; o++) {
        float val = fminf(1.f, fmaxf(-1.f, acc[o]));
        int idx = ((b*18 + o)*HH + h)*WW + w;
        g_off[idx] = val;
        if (outoff) outoff[idx] = val;
    }
}

// ---------------------------------------------------------------------------
// Main deformable conv with warp-level bf16 HMMA (mma.sync m16n8k16).
// Block = 128 pixels x 64 couts, K=576 split into 9 taps x 64 ch.
// Per tap: gather bilinear -> A[128px][64ch] bf16 hi/lo (SW128 smem),
//          weights -> B[64ch][64cout] bf16 hi/lo (SW128 smem),
//          8 warps: warp w = pixel rows 16w..16w+15, all 8 n-tiles,
//          3 MMAs per (kstep, ntile): AhBh + AhBl + AlBh.
// ---------------------------------------------------------------------------
#define SM_A_HI 0
#define SM_A_LO 16384
#define SM_B_HI 32768
#define SM_B_LO 40960
#define SM_PB   49152
#define SM_PW   51200
#define SM_SIZE (53248 + 1024)

__global__ __launch_bounds__(256, 3) void k_deform(float* __restrict__ out) {
    extern __shared__ char smraw[];
    char* sm = (char*)(((uintptr_t)smraw + 1023) & ~(uintptr_t)1023);
    uint32_t s0 = smem_u32(sm);
    int tid = threadIdx.x, wid = tid >> 5, lid = tid & 31;
    int tile = blockIdx.x;            // 0..799
    int b = tile / 200;
    int px0 = (tile % 200) * 128;     // within-batch pixel base

    int*   sPB = (int*)(sm + SM_PB);
    float* sPW = (float*)(sm + SM_PW);
    const float4* xp = (const float4*)g_xh;

    float acc[8][4];
    #pragma unroll
    for (int j = 0; j < 8; j++)
        #pragma unroll
        for (int q = 0; q < 4; q++) acc[j][q] = 0.f;

    for (int tap = 0; tap < 9; tap++) {
        // ---- coords: 128 px, 2 corners per thread ----
        {
            int px = tid >> 1;
            int pg = px0 + px;
            int h = pg / WW, w = pg % WW;
            float dy = g_off[(b*18 + 2*tap    )*HW + pg];
            float dx = g_off[(b*18 + 2*tap + 1)*HW + pg];
            float py = (float)h - 1.f + (float)(tap / 3) + dy;
            float pxx = (float)w - 1.f + (float)(tap % 3) + dx;
            float y0f = floorf(py), x0f = floorf(pxx);
            float fy = py - y0f, fx = pxx - x0f;
            int y0 = (int)y0f, x0 = (int)x0f;
            #pragma unroll
            for (int j = 0; j < 2; j++) {
                int cn = (tid & 1) * 2 + j;
                int yy = y0 + (cn >> 1), xx = x0 + (cn & 1);
                float wt = ((cn >> 1) ? fy : 1.f - fy) * ((cn & 1) ? fx : 1.f - fx);
                bool valid = (yy >= 0) && (yy < HH) && (xx >= 0) && (xx < WW);
                int yc = min(max(yy, 0), HH - 1), xc = min(max(xx, 0), WW - 1);
                sPB[cn*128 + px] = ((b*HH + yc)*WW + xc) * CC;
                sPW[cn*128 + px] = valid ? wt : 0.f;
            }
        }
        __syncthreads();

        // ---- gather -> A hi/lo (SW128) ----
        {
            int g4 = tid & 15;                 // channel group of 4
            #pragma unroll 2
            for (int it = 0; it < 8; it++) {
                int px = (tid >> 4) + it * 16;
                int b0 = sPB[px],       b1 = sPB[128 + px];
                int b2 = sPB[256 + px], b3 = sPB[384 + px];
                float w0 = sPW[px],       w1 = sPW[128 + px];
                float w2 = sPW[256 + px], w3 = sPW[384 + px];
                float4 a0 = xp[(b0 >> 2) + g4];
                float4 a1 = xp[(b1 >> 2) + g4];
                float4 a2 = xp[(b2 >> 2) + g4];
                float4 a3 = xp[(b3 >> 2) + g4];
                float4 v;
                v.x = w0*a0.x + w1*a1.x + w2*a2.x + w3*a3.x;
                v.y = w0*a0.y + w1*a1.y + w2*a2.y + w3*a3.y;
                v.z = w0*a0.z + w1*a1.z + w2*a2.z + w3*a3.z;
                v.w = w0*a0.w + w1*a1.w + w2*a2.w + w3*a3.w;
                __nv_bfloat162 h01 = __floats2bfloat162_rn(v.x, v.y);
                __nv_bfloat162 h23 = __floats2bfloat162_rn(v.z, v.w);
                __nv_bfloat162 l01 = __floats2bfloat162_rn(
                    v.x - __bfloat162float(h01.x), v.y - __bfloat162float(h01.y));
                __nv_bfloat162 l23 = __floats2bfloat162_rn(
                    v.z - __bfloat162float(h23.x), v.w - __bfloat162float(h23.y));
                uint32_t sw = sw128(px * 128 + g4 * 8);
                uint2 hv, lv;
                hv.x = *(uint32_t*)&h01; hv.y = *(uint32_t*)&h23;
                lv.x = *(uint32_t*)&l01; lv.y = *(uint32_t*)&l23;
                *(uint2*)(sm + SM_A_HI + sw) = hv;
                *(uint2*)(sm + SM_A_LO + sw) = lv;
            }
        }

        // ---- weights chunk -> B hi/lo (SW128): [64 cin][64 cout] ----
        {
            const uint4* wh = (const uint4*)g_wbh + tap * 512;
            const uint4* wl = (const uint4*)g_wbl + tap * 512;
            #pragma unroll
            for (int i = tid; i < 512; i += 256) {
                int row = i >> 3, gq = i & 7;          // row=cin, gq=cout grp of 8
                uint32_t sw = sw128(row * 128 + gq * 16);
                *(uint4*)(sm + SM_B_HI + sw) = wh[i];
                *(uint4*)(sm + SM_B_LO + sw) = wl[i];
            }
        }
        __syncthreads();

        // ---- MMA phase: warp w -> px rows 16w..16w+15 ----
        {
            int arow = wid * 16 + (lid & 15);
            int ahalf = (lid >> 4) * 8;
            int blrow = lid & 15;
            int bnoff = (lid >> 4) * 8;
            #pragma unroll
            for (int ks = 0; ks < 4; ks++) {
                int k0 = ks * 16;
                uint32_t sa = sw128(arow * 128 + (k0 + ahalf) * 2);
                uint32_t ah0, ah1, ah2, ah3, al0, al1, al2, al3;
                ldsm_x4(ah0, ah1, ah2, ah3, s0 + SM_A_HI + sa);
                ldsm_x4(al0, al1, al2, al3, s0 + SM_A_LO + sa);
                #pragma unroll
                for (int jj = 0; jj < 4; jj++) {
                    uint32_t sb = sw128((k0 + blrow) * 128 + (jj*16 + bnoff) * 2);
                    uint32_t bh0, bh1, bh2, bh3, bl0, bl1, bl2, bl3;
                    ldsm_x4t(bh0, bh1, bh2, bh3, s0 + SM_B_HI + sb);
                    ldsm_x4t(bl0, bl1, bl2, bl3, s0 + SM_B_LO + sb);
                    mma16816(acc[2*jj],   ah0, ah1, ah2, ah3, bh0, bh1);
                    mma16816(acc[2*jj],   ah0, ah1, ah2, ah3, bl0, bl1);
                    mma16816(acc[2*jj],   al0, al1, al2, al3, bh0, bh1);
                    mma16816(acc[2*jj+1], ah0, ah1, ah2, ah3, bh2, bh3);
                    mma16816(acc[2*jj+1], ah0, ah1, ah2, ah3, bl2, bl3);
                    mma16816(acc[2*jj+1], al0, al1, al2, al3, bh2, bh3);
                }
            }
        }
        __syncthreads();   // tiles free for next tap
    }

    // ---- epilogue: fragments -> NCHW ----
    {
        int prow = px0 + wid * 16 + (lid >> 2);
        float* op = out + (size_t)b * COUT * HW;
        #pragma unroll
        for (int j = 0; j < 8; j++) {
            int c0 = j * 8 + (lid & 3) * 2;
            op[(c0    ) * HW + prow    ] = acc[j][0];
            op[(c0 + 1) * HW + prow    ] = acc[j][1];
            op[(c0    ) * HW + prow + 8] = acc[j][2];
            op[(c0 + 1) * HW + prow + 8] = acc[j][3];
        }
    }
}

// ---------------------------------------------------------------------------
// BN stats + apply
// ---------------------------------------------------------------------------
__global__ void k_stats(const float* __restrict__ out) {
    int c = blockIdx.x, bi = blockIdx.y;
    float s = 0.f, sq = 0.f;
    for (int n = bi * 256 + threadIdx.x; n < BB * HW; n += gridDim.y * 256) {
        int b = n / HW, i = n - b * HW;
        float v = out[(b * COUT + c) * HW + i];
        s += v; sq += v * v;
    }
    __shared__ float rs[256], rq[256];
    rs[threadIdx.x] = s; rq[threadIdx.x] = sq;
    __syncthreads();
    for (int st = 128; st > 0; st >>= 1) {
        if (threadIdx.x < st) {
            rs[threadIdx.x] += rs[threadIdx.x + st];
            rq[threadIdx.x] += rq[threadIdx.x + st];
        }
        __syncthreads();
    }
    if (threadIdx.x == 0) {
        g_part[(c * 16 + bi) * 2]     = rs[0];
        g_part[(c * 16 + bi) * 2 + 1] = rq[0];
    }
}

__global__ void k_finalize(const float* __restrict__ gamma,
                           const float* __restrict__ beta) {
    int c = threadIdx.x;
    if (c < COUT) {
        float s = 0.f, sq = 0.f;
        for (int i = 0; i < 16; i++) {
            s  += g_part[(c * 16 + i) * 2];
            sq += g_part[(c * 16 + i) * 2 + 1];
        }
        float inv_n = 1.f / (float)(BB * HW);
        float mean = s * inv_n;
        float var  = sq * inv_n - mean * mean;
        float sc = gamma[c] * rsqrtf(var + EPSV);
        g_scale[c] = sc;
        g_shift[c] = beta[c] - mean * sc;
    }
}

__global__ void k_bnrelu(float* __restrict__ out) {
    int idx = blockIdx.x * 256 + threadIdx.x;
    int c = (idx / (HW / 4)) & 63;
    float sc = g_scale[c], sh = g_shift[c];
    float4 v = ((float4*)out)[idx];
    v.x = fmaxf(0.f, v.x * sc + sh);
    v.y = fmaxf(0.f, v.y * sc + sh);
    v.z = fmaxf(0.f, v.z * sc + sh);
    v.w = fmaxf(0.f, v.w * sc + sh);
    ((float4*)out)[idx] = v;
}

// ---------------------------------------------------------------------------
extern "C" void kernel_launch(void* const* d_in, const int* in_sizes, int n_in,
                              void* d_out, int out_size) {
    const float* x     = (const float*)d_in[0];
    const float* d     = (const float*)d_in[1];
    const float* ow    = (const float*)d_in[2];
    const float* cw    = (const float*)d_in[3];
    const float* gamma = (const float*)d_in[4];
    const float* beta  = (const float*)d_in[5];
    float* out = (float*)d_out;
    float* outoff = (out_size >= OUT_MAIN + OUT_OFF) ? (out + OUT_MAIN) : nullptr;

    cudaFuncSetAttribute(k_deform, cudaFuncAttributeMaxDynamicSharedMemorySize,
                         SM_SIZE);

    k_transpose<<<dim3(10, BB * HH, 1), dim3(32, 8)>>>(x);
    k_wsplit<<<(K2 * CC * COUT + 255) / 256, 256>>>(cw);
    k_offconv<<<dim3(5, 20, BB), 256>>>(d, ow, outoff);
    k_deform<<<800, 256, SM_SIZE>>>(out);
    k_stats<<<dim3(COUT, 16), 256>>>(out);
    k_finalize<<<1, 64>>>(gamma, beta);
    k_bnrelu<<<OUT_MAIN / 4 / 256, 256>>>(out);
}

// round 4
// speedup vs baseline: 2.7006x; 1.0002x over previous
#include <cuda_runtime.h>
#include <cuda_bf16.h>
#include <cstdint>

#define HH 160
#define WW 160
#define BB 4
#define CC 64
#define COUT 64
#define OFFC 64
#define K2 9
#define HW (HH*WW)             // 25600
#define OUT_MAIN (BB*COUT*HW)  // 6553600
#define OUT_OFF  (BB*2*K2*HW)  // 1843200
#define EPSV 1e-5f

// ---- warp-MMA helpers (plain PTX, works on .target sm_103) ----------------
__device__ __forceinline__ uint32_t smem_u32(const void* p) {
    uint32_t a;
    asm("{ .reg .u64 t; cvta.to.shared.u64 t, %1; cvt.u32.u64 %0, t; }"
        : "=r"(a) : "l"(p));
    return a;
}
__device__ __forceinline__ void ldsm_x4(uint32_t& r0, uint32_t& r1,
                                        uint32_t& r2, uint32_t& r3, uint32_t a) {
    asm volatile("ldmatrix.sync.aligned.m8n8.x4.shared.b16 {%0,%1,%2,%3}, [%4];"
                 : "=r"(r0), "=r"(r1), "=r"(r2), "=r"(r3) : "r"(a));
}
__device__ __forceinline__ void ldsm_x4t(uint32_t& r0, uint32_t& r1,
                                         uint32_t& r2, uint32_t& r3, uint32_t a) {
    asm volatile("ldmatrix.sync.aligned.m8n8.x4.trans.shared.b16 {%0,%1,%2,%3}, [%4];"
                 : "=r"(r0), "=r"(r1), "=r"(r2), "=r"(r3) : "r"(a));
}
__device__ __forceinline__ void mma16816(float* c, const uint32_t* a,
                                         uint32_t b0, uint32_t b1) {
    asm volatile("mma.sync.aligned.m16n8k16.row.col.f32.bf16.bf16.f32 "
                 "{%0,%1,%2,%3}, {%4,%5,%6,%7}, {%8,%9}, {%0,%1,%2,%3};"
                 : "+f"(c[0]), "+f"(c[1]), "+f"(c[2]), "+f"(c[3])
                 : "r"(a[0]), "r"(a[1]), "r"(a[2]), "r"(a[3]), "r"(b0), "r"(b1));
}
__device__ __forceinline__ void ffma2(unsigned long long& d,
                                      unsigned long long a, unsigned long long b) {
    asm("fma.rn.f32x2 %0, %1, %2, %0;" : "+l"(d) : "l"(a), "l"(b));
}
__device__ __forceinline__ uint32_t sw128(uint32_t off) {
    return off ^ ((off >> 3) & 0x70);
}

// ---- global scratch -------------------------------------------------------
__device__ float g_xh[BB*HW*CC];                 // x in NHWC fp32
__device__ __nv_bfloat16 g_wbh[K2*CC*COUT];      // W hi  [tap][cin][cout]
__device__ __nv_bfloat16 g_wbl[K2*CC*COUT];      // W lo
__device__ float g_off[BB*2*K2*HW];              // clamped offsets NCHW
__device__ float g_part[COUT*16*2];
__device__ float g_scale[COUT];
__device__ float g_shift[COUT];

// ---------------------------------------------------------------------------
// NCHW -> NHWC transpose of x
// ---------------------------------------------------------------------------
__global__ void k_transpose(const float* __restrict__ x) {
    __shared__ float tile[32][33];
    int bh = blockIdx.y;
    int b = bh / HH, h = bh % HH;
    int tw = blockIdx.x % 5, tc = blockIdx.x / 5;
    int w = tw * 32 + threadIdx.x;
    #pragma unroll
    for (int i = 0; i < 4; i++) {
        int cl = threadIdx.y + i * 8;
        tile[cl][threadIdx.x] = x[((b*CC + tc*32 + cl)*HH + h)*WW + w];
    }
    __syncthreads();
    #pragma unroll
    for (int i = 0; i < 4; i++) {
        int wl = threadIdx.y + i * 8;
        g_xh[((b*HH + h)*WW + tw*32 + wl)*CC + tc*32 + threadIdx.x]
            = tile[threadIdx.x][wl];
    }
}

// ---------------------------------------------------------------------------
// Split conv_w into bf16 hi/lo, reorder to [tap][cin][cout]
// ---------------------------------------------------------------------------
__global__ void k_wsplit(const float* __restrict__ cw) {
    int i = blockIdx.x * 256 + threadIdx.x;      // K2*CC*COUT = 36864
    if (i < K2*CC*COUT) {
        int tap = i / (CC*COUT), ci = (i / COUT) % CC, co = i % COUT;
        float w = cw[(co*CC + ci)*K2 + tap];
        __nv_bfloat16 h = __float2bfloat16(w);
        float lo = w - __bfloat162float(h);
        g_wbh[i] = h;
        g_wbl[i] = __float2bfloat16(lo);
    }
}

// ---------------------------------------------------------------------------
// Offset branch: 3x3 conv(d, offset_w), clamp to [-1,1].
// Packed f32x2: each thread computes a vertical pixel pair (ty, ty+8).
// Weights pre-duplicated in smem: wsm4[c][t][op] = (w[2op],w[2op],w[2op+1],w[2op+1]).
// Tile 32w x 16h, block 256, grid (5,10,B). Dynamic smem ~84KB, 2 CTAs/SM.
// ---------------------------------------------------------------------------
#define WSM4_ELEMS (OFFC * 9 * 9)            // 5184 float4
#define SMEM_OFF_SIZE (WSM4_ELEMS * 16 + 10 * 34 * 8)

__global__ __launch_bounds__(256, 2) void k_offconv(
        const float* __restrict__ d, const float* __restrict__ ow,
        float* __restrict__ outoff) {
    extern __shared__ char osm[];
    float4* wsm4 = (float4*)osm;                       // [64][9][9]
    float2* tsm2 = (float2*)(osm + WSM4_ELEMS * 16);   // [10][34]
    int tid = threadIdx.x;
    // build duplicated weights
    for (int i = tid; i < WSM4_ELEMS; i += 256) {
        int c = i / 81, rem = i % 81, t = rem / 9, op = rem % 9;
        float w0 = ow[(2*op    ) * (OFFC*9) + c*9 + t];
        float w1 = ow[(2*op + 1) * (OFFC*9) + c*9 + t];
        wsm4[i] = make_float4(w0, w0, w1, w1);
    }
    int b = blockIdx.z;
    int h0 = blockIdx.y * 16, w0 = blockIdx.x * 32;
    int tx = tid & 31, ty = tid >> 5;                 // ty in 0..7
    unsigned long long acc2[18];
    #pragma unroll
    for (int o = 0; o < 18; o++) acc2[o] = 0ULL;

    for (int c = 0; c < OFFC; c++) {
        __syncthreads();
        // load tile rows 0..17 (y = h0+r-1), cols 0..33 (x = w0+cc-1)
        for (int i = tid; i < 18 * 34; i += 256) {
            int r = i / 34, cc = i % 34;
            int y = h0 + r - 1, x = w0 + cc - 1;
            float v = 0.f;
            if (y >= 0 && y < HH && x >= 0 && x < WW)
                v = d[((b*OFFC + c)*HH + y)*WW + x];
            if (r < 10) ((float*)&tsm2[r * 34 + cc])[0] = v;
            if (r >= 8) ((float*)&tsm2[(r - 8) * 34 + cc])[1] = v;
        }
        __syncthreads();
        unsigned long long v2[9];
        #pragma unroll
        for (int t = 0; t < 9; t++)
            v2[t] = *(const unsigned long long*)&tsm2[(ty + t/3) * 34 + tx + t%3];
        const float4* wc = wsm4 + c * 81;
        #pragma unroll
        for (int t = 0; t < 9; t++) {
            #pragma unroll
            for (int op = 0; op < 9; op++) {
                ulonglong2 w = *(const ulonglong2*)&wc[t * 9 + op];
                ffma2(acc2[2*op    ], v2[t], w.x);
                ffma2(acc2[2*op + 1], v2[t], w.y);
            }
        }
    }
    #pragma unroll
    for (int o = 0; o < 18; o++) {
        float vx = __uint_as_float((unsigned)(acc2[o] & 0xffffffffu));
        float vy = __uint_as_float((unsigned)(acc2[o] >> 32));
        vx = fminf(1.f, fmaxf(-1.f, vx));
        vy = fminf(1.f, fmaxf(-1.f, vy));
        int i0 = ((b*18 + o)*HH + h0 + ty    )*WW + w0 + tx;
        int i1 = ((b*18 + o)*HH + h0 + ty + 8)*WW + w0 + tx;
        g_off[i0] = vx;
        g_off[i1] = vy;
        if (outoff) { outoff[i0] = vx; outoff[i1] = vy; }
    }
}

// ---------------------------------------------------------------------------
// Main deformable conv with warp-level bf16 HMMA (mma.sync m16n8k16).
// Block = 128 pixels x 64 couts, K=576 split into 9 taps x 64 ch.
// Warp tiling 4M x 2N: warp = (M32, N32) -> halves B-ldsm replication.
// ---------------------------------------------------------------------------
#define SM_A_HI 0
#define SM_A_LO 16384
#define SM_B_HI 32768
#define SM_B_LO 40960
#define SM_PBW  49152
#define SM_SIZE (53248 + 1024)

__global__ __launch_bounds__(256, 3) void k_deform(float* __restrict__ out) {
    extern __shared__ char smraw[];
    char* sm = (char*)(((uintptr_t)smraw + 1023) & ~(uintptr_t)1023);
    uint32_t s0 = smem_u32(sm);
    int tid = threadIdx.x, wid = tid >> 5, lid = tid & 31;
    int tile = blockIdx.x;            // 0..799
    int b = tile / 200;
    int px0 = (tile % 200) * 128;

    int2* sBW = (int2*)(sm + SM_PBW);              // [4 corners][128 px]
    const float4* xp = (const float4*)g_xh;

    int mw = wid & 3, nw = wid >> 2;
    int l15 = lid & 15, l16 = (lid >> 4) * 8;

    float acc[2][4][4];
    #pragma unroll
    for (int mt = 0; mt < 2; mt++)
        #pragma unroll
        for (int j = 0; j < 4; j++)
            #pragma unroll
            for (int q = 0; q < 4; q++) acc[mt][j][q] = 0.f;

    for (int tap = 0; tap < 9; tap++) {
        // ---- coords: 128 px, 2 corners per thread ----
        {
            int px = tid >> 1;
            int pg = px0 + px;
            int h = pg / WW, w = pg % WW;
            float dy = g_off[(b*18 + 2*tap    )*HW + pg];
            float dx = g_off[(b*18 + 2*tap + 1)*HW + pg];
            float py = (float)h - 1.f + (float)(tap / 3) + dy;
            float pxx = (float)w - 1.f + (float)(tap % 3) + dx;
            float y0f = floorf(py), x0f = floorf(pxx);
            float fy = py - y0f, fx = pxx - x0f;
            int y0 = (int)y0f, x0 = (int)x0f;
            #pragma unroll
            for (int j = 0; j < 2; j++) {
                int cn = (tid & 1) * 2 + j;
                int yy = y0 + (cn >> 1), xx = x0 + (cn & 1);
                float wt = ((cn >> 1) ? fy : 1.f - fy) * ((cn & 1) ? fx : 1.f - fx);
                bool valid = (yy >= 0) && (yy < HH) && (xx >= 0) && (xx < WW);
                int yc = min(max(yy, 0), HH - 1), xc = min(max(xx, 0), WW - 1);
                sBW[cn*128 + px] = make_int2(((b*HH + yc)*WW + xc) * CC,
                                             __float_as_int(valid ? wt : 0.f));
            }
        }
        __syncthreads();

        // ---- gather -> A hi/lo (SW128) ----
        {
            int g4 = tid & 15;                 // channel group of 4
            #pragma unroll 2
            for (int it = 0; it < 8; it++) {
                int px = (tid >> 4) + it * 16;
                int2 q0 = sBW[px],       q1 = sBW[128 + px];
                int2 q2 = sBW[256 + px], q3 = sBW[384 + px];
                float w0 = __int_as_float(q0.y), w1 = __int_as_float(q1.y);
                float w2 = __int_as_float(q2.y), w3 = __int_as_float(q3.y);
                float4 a0 = xp[(q0.x >> 2) + g4];
                float4 a1 = xp[(q1.x >> 2) + g4];
                float4 a2 = xp[(q2.x >> 2) + g4];
                float4 a3 = xp[(q3.x >> 2) + g4];
                float4 v;
                v.x = w0*a0.x + w1*a1.x + w2*a2.x + w3*a3.x;
                v.y = w0*a0.y + w1*a1.y + w2*a2.y + w3*a3.y;
                v.z = w0*a0.z + w1*a1.z + w2*a2.z + w3*a3.z;
                v.w = w0*a0.w + w1*a1.w + w2*a2.w + w3*a3.w;
                __nv_bfloat162 h01 = __floats2bfloat162_rn(v.x, v.y);
                __nv_bfloat162 h23 = __floats2bfloat162_rn(v.z, v.w);
                __nv_bfloat162 l01 = __floats2bfloat162_rn(
                    v.x - __bfloat162float(h01.x), v.y - __bfloat162float(h01.y));
                __nv_bfloat162 l23 = __floats2bfloat162_rn(
                    v.z - __bfloat162float(h23.x), v.w - __bfloat162float(h23.y));
                uint32_t sw = sw128(px * 128 + g4 * 8);
                uint2 hv, lv;
                hv.x = *(uint32_t*)&h01; hv.y = *(uint32_t*)&h23;
                lv.x = *(uint32_t*)&l01; lv.y = *(uint32_t*)&l23;
                *(uint2*)(sm + SM_A_HI + sw) = hv;
                *(uint2*)(sm + SM_A_LO + sw) = lv;
            }
        }

        // ---- weights chunk -> B hi/lo (SW128): [64 cin][64 cout] ----
        {
            const uint4* wh = (const uint4*)g_wbh + tap * 512;
            const uint4* wl = (const uint4*)g_wbl + tap * 512;
            #pragma unroll
            for (int i = tid; i < 512; i += 256) {
                int row = i >> 3, gq = i & 7;
                uint32_t sw = sw128(row * 128 + gq * 16);
                *(uint4*)(sm + SM_B_HI + sw) = wh[i];
                *(uint4*)(sm + SM_B_LO + sw) = wl[i];
            }
        }
        __syncthreads();

        // ---- MMA phase: warp (mw, nw) -> px rows 32mw..+31, couts 32nw..+31 ----
        #pragma unroll
        for (int ks = 0; ks < 4; ks++) {
            int k0 = ks * 16;
            uint32_t ah[2][4], al[2][4];
            #pragma unroll
            for (int mt = 0; mt < 2; mt++) {
                uint32_t sa = sw128((mw*32 + mt*16 + l15) * 128 + (k0 + l16) * 2);
                ldsm_x4(ah[mt][0], ah[mt][1], ah[mt][2], ah[mt][3], s0 + SM_A_HI + sa);
                ldsm_x4(al[mt][0], al[mt][1], al[mt][2], al[mt][3], s0 + SM_A_LO + sa);
            }
            #pragma unroll
            for (int jj = 0; jj < 2; jj++) {
                uint32_t sb = sw128((k0 + l15) * 128 + (nw*32 + jj*16 + l16) * 2);
                uint32_t bh0, bh1, bh2, bh3, bl0, bl1, bl2, bl3;
                ldsm_x4t(bh0, bh1, bh2, bh3, s0 + SM_B_HI + sb);
                ldsm_x4t(bl0, bl1, bl2, bl3, s0 + SM_B_LO + sb);
                #pragma unroll
                for (int mt = 0; mt < 2; mt++) {
                    mma16816(acc[mt][2*jj],   ah[mt], bh0, bh1);
                    mma16816(acc[mt][2*jj],   ah[mt], bl0, bl1);
                    mma16816(acc[mt][2*jj],   al[mt], bh0, bh1);
                    mma16816(acc[mt][2*jj+1], ah[mt], bh2, bh3);
                    mma16816(acc[mt][2*jj+1], ah[mt], bl2, bl3);
                    mma16816(acc[mt][2*jj+1], al[mt], bh2, bh3);
                }
            }
        }
        __syncthreads();
    }

    // ---- epilogue: fragments -> NCHW ----
    {
        float* op = out + (size_t)b * COUT * HW;
        #pragma unroll
        for (int mt = 0; mt < 2; mt++) {
            int prow = px0 + mw*32 + mt*16 + (lid >> 2);
            #pragma unroll
            for (int j = 0; j < 4; j++) {
                int c0 = nw*32 + j*8 + (lid & 3) * 2;
                op[(c0    ) * HW + prow    ] = acc[mt][j][0];
                op[(c0 + 1) * HW + prow    ] = acc[mt][j][1];
                op[(c0    ) * HW + prow + 8] = acc[mt][j][2];
                op[(c0 + 1) * HW + prow + 8] = acc[mt][j][3];
            }
        }
    }
}

// ---------------------------------------------------------------------------
// BN stats + apply
// ---------------------------------------------------------------------------
__global__ void k_stats(const float* __restrict__ out) {
    int c = blockIdx.x, bi = blockIdx.y;
    float s = 0.f, sq = 0.f;
    for (int n = bi * 256 + threadIdx.x; n < BB * HW / 4; n += gridDim.y * 256) {
        int b = n / (HW/4), i = n - b * (HW/4);
        float4 v = ((const float4*)(out + (b * COUT + c) * HW))[i];
        s  += v.x + v.y + v.z + v.w;
        sq += v.x*v.x + v.y*v.y + v.z*v.z + v.w*v.w;
    }
    __shared__ float rs[256], rq[256];
    rs[threadIdx.x] = s; rq[threadIdx.x] = sq;
    __syncthreads();
    for (int st = 128; st > 0; st >>= 1) {
        if (threadIdx.x < st) {
            rs[threadIdx.x] += rs[threadIdx.x + st];
            rq[threadIdx.x] += rq[threadIdx.x + st];
        }
        __syncthreads();
    }
    if (threadIdx.x == 0) {
        g_part[(c * 16 + bi) * 2]     = rs[0];
        g_part[(c * 16 + bi) * 2 + 1] = rq[0];
    }
}

__global__ void k_finalize(const float* __restrict__ gamma,
                           const float* __restrict__ beta) {
    int c = threadIdx.x;
    if (c < COUT) {
        float s = 0.f, sq = 0.f;
        for (int i = 0; i < 16; i++) {
            s  += g_part[(c * 16 + i) * 2];
            sq += g_part[(c * 16 + i) * 2 + 1];
        }
        float inv_n = 1.f / (float)(BB * HW);
        float mean = s * inv_n;
        float var  = sq * inv_n - mean * mean;
        float sc = gamma[c] * rsqrtf(var + EPSV);
        g_scale[c] = sc;
        g_shift[c] = beta[c] - mean * sc;
    }
}

__global__ void k_bnrelu(float* __restrict__ out) {
    int idx = blockIdx.x * 256 + threadIdx.x;
    int c = (idx / (HW / 4)) & 63;
    float sc = g_scale[c], sh = g_shift[c];
    float4 v = ((float4*)out)[idx];
    v.x = fmaxf(0.f, v.x * sc + sh);
    v.y = fmaxf(0.f, v.y * sc + sh);
    v.z = fmaxf(0.f, v.z * sc + sh);
    v.w = fmaxf(0.f, v.w * sc + sh);
    ((float4*)out)[idx] = v;
}

// ---------------------------------------------------------------------------
extern "C" void kernel_launch(void* const* d_in, const int* in_sizes, int n_in,
                              void* d_out, int out_size) {
    const float* x     = (const float*)d_in[0];
    const float* d     = (const float*)d_in[1];
    const float* ow    = (const float*)d_in[2];
    const float* cw    = (const float*)d_in[3];
    const float* gamma = (const float*)d_in[4];
    const float* beta  = (const float*)d_in[5];
    float* out = (float*)d_out;
    float* outoff = (out_size >= OUT_MAIN + OUT_OFF) ? (out + OUT_MAIN) : nullptr;

    cudaFuncSetAttribute(k_deform, cudaFuncAttributeMaxDynamicSharedMemorySize,
                         SM_SIZE);
    cudaFuncSetAttribute(k_offconv, cudaFuncAttributeMaxDynamicSharedMemorySize,
                         SMEM_OFF_SIZE);

    k_transpose<<<dim3(10, BB * HH, 1), dim3(32, 8)>>>(x);
    k_wsplit<<<(K2 * CC * COUT + 255) / 256, 256>>>(cw);
    k_offconv<<<dim3(5, 10, BB), 256, SMEM_OFF_SIZE>>>(d, ow, outoff);
    k_deform<<<800, 256, SM_SIZE>>>(out);
    k_stats<<<dim3(COUT, 16), 256>>>(out);
    k_finalize<<<1, 64>>>(gamma, beta);
    k_bnrelu<<<OUT_MAIN / 4 / 256, 256>>>(out);
}

// round 6
// speedup vs baseline: 3.7254x; 1.3795x over previous
#include <cuda_runtime.h>
#include <cuda_bf16.h>
#include <cstdint>

#define HH 160
#define WW 160
#define BB 4
#define CC 64
#define COUT 64
#define OFFC 64
#define K2 9
#define HW (HH*WW)             // 25600
#define OUT_MAIN (BB*COUT*HW)  // 6553600
#define OUT_OFF  (BB*2*K2*HW)  // 1843200
#define EPSV 1e-5f

// ---- warp-MMA helpers (plain PTX, works on .target sm_103) ----------------
__device__ __forceinline__ uint32_t smem_u32(const void* p) {
    uint32_t a;
    asm("{ .reg .u64 t; cvta.to.shared.u64 t, %1; cvt.u32.u64 %0, t; }"
        : "=r"(a) : "l"(p));
    return a;
}
__device__ __forceinline__ void ldsm_x4(uint32_t& r0, uint32_t& r1,
                                        uint32_t& r2, uint32_t& r3, uint32_t a) {
    asm volatile("ldmatrix.sync.aligned.m8n8.x4.shared.b16 {%0,%1,%2,%3}, [%4];"
                 : "=r"(r0), "=r"(r1), "=r"(r2), "=r"(r3) : "r"(a));
}
__device__ __forceinline__ void ldsm_x4t(uint32_t& r0, uint32_t& r1,
                                         uint32_t& r2, uint32_t& r3, uint32_t a) {
    asm volatile("ldmatrix.sync.aligned.m8n8.x4.trans.shared.b16 {%0,%1,%2,%3}, [%4];"
                 : "=r"(r0), "=r"(r1), "=r"(r2), "=r"(r3) : "r"(a));
}
__device__ __forceinline__ void mma16816(float* c, const uint32_t* a,
                                         uint32_t b0, uint32_t b1) {
    asm volatile("mma.sync.aligned.m16n8k16.row.col.f32.bf16.bf16.f32 "
                 "{%0,%1,%2,%3}, {%4,%5,%6,%7}, {%8,%9}, {%0,%1,%2,%3};"
                 : "+f"(c[0]), "+f"(c[1]), "+f"(c[2]), "+f"(c[3])
                 : "r"(a[0]), "r"(a[1]), "r"(a[2]), "r"(a[3]), "r"(b0), "r"(b1));
}
__device__ __forceinline__ uint32_t sw128(uint32_t off) {
    return off ^ ((off >> 3) & 0x70);
}

// ---- global scratch -------------------------------------------------------
__device__ float g_xh[BB*HW*CC];                 // x in NHWC fp32
__device__ float g_dh[BB*HW*CC];                 // d in NHWC fp32
__device__ __nv_bfloat16 g_wbh[K2*CC*COUT];      // conv W hi [tap][cin][cout]
__device__ __nv_bfloat16 g_wbl[K2*CC*COUT];      // conv W lo
__device__ __nv_bfloat16 g_obh[K2*OFFC*64];      // offset W hi [tap][cin][cout64pad]
__device__ __nv_bfloat16 g_obl[K2*OFFC*64];      // offset W lo
__device__ float g_off[BB*2*K2*HW];              // clamped offsets NCHW
__device__ float g_part[COUT*16*2];
__device__ float g_scale[COUT];
__device__ float g_shift[COUT];

// ---------------------------------------------------------------------------
// NCHW -> NHWC transpose of x (z=0) and d (z=1)
// ---------------------------------------------------------------------------
__global__ void k_transpose(const float* __restrict__ x,
                            const float* __restrict__ d) {
    __shared__ float tile[32][33];
    const float* src = blockIdx.z ? d : x;
    float* dst = blockIdx.z ? g_dh : g_xh;
    int bh = blockIdx.y;
    int b = bh / HH, h = bh % HH;
    int tw = blockIdx.x % 5, tc = blockIdx.x / 5;
    int w = tw * 32 + threadIdx.x;
    #pragma unroll
    for (int i = 0; i < 4; i++) {
        int cl = threadIdx.y + i * 8;
        tile[cl][threadIdx.x] = src[((b*CC + tc*32 + cl)*HH + h)*WW + w];
    }
    __syncthreads();
    #pragma unroll
    for (int i = 0; i < 4; i++) {
        int wl = threadIdx.y + i * 8;
        dst[((b*HH + h)*WW + tw*32 + wl)*CC + tc*32 + threadIdx.x]
            = tile[threadIdx.x][wl];
    }
}

// ---------------------------------------------------------------------------
// Split conv_w into bf16 hi/lo, [tap][cin][cout]
// ---------------------------------------------------------------------------
__global__ void k_wsplit(const float* __restrict__ cw) {
    int i = blockIdx.x * 256 + threadIdx.x;      // K2*CC*COUT = 36864
    if (i < K2*CC*COUT) {
        int tap = i / (CC*COUT), ci = (i / COUT) % CC, co = i % COUT;
        float w = cw[(co*CC + ci)*K2 + tap];
        __nv_bfloat16 h = __float2bfloat16(w);
        float lo = w - __bfloat162float(h);
        g_wbh[i] = h;
        g_wbl[i] = __float2bfloat16(lo);
    }
}

// ---------------------------------------------------------------------------
// Split offset_w into bf16 hi/lo, [tap][cin][64pad] (couts 18..63 zero)
// ---------------------------------------------------------------------------
__global__ void k_owsplit(const float* __restrict__ ow) {
    int i = blockIdx.x * 256 + threadIdx.x;      // K2*OFFC*64 = 36864
    if (i < K2*OFFC*64) {
        int tap = i / (OFFC*64), ci = (i / 64) % OFFC, co = i % 64;
        float w = 0.f;
        if (co < 18) w = ow[(co*OFFC + ci)*K2 + tap];
        __nv_bfloat16 h = __float2bfloat16(w);
        float lo = w - __bfloat162float(h);
        g_obh[i] = h;
        g_obl[i] = __float2bfloat16(lo);
    }
}

// ---------------------------------------------------------------------------
// Offset conv as HMMA GEMM: [128px x 576] x [576 x 32(pad of 18)].
// Per tap: shift-gather d (NHWC) -> A bf16 hi/lo (SW128), B tile from
// g_obh/g_obl, 8 warps each M16/N32, 48 MMAs per warp-tap.
// Epilogue: clamp, write g_off (NCHW) + outoff.
// ---------------------------------------------------------------------------
#define OSM_A_HI 0
#define OSM_A_LO 16384
#define OSM_B_HI 32768
#define OSM_B_LO 40960
#define OSM_SIZE (49152 + 1024)

__global__ __launch_bounds__(256, 4) void k_offmma(float* __restrict__ outoff) {
    extern __shared__ char smraw[];
    char* sm = (char*)(((uintptr_t)smraw + 1023) & ~(uintptr_t)1023);
    uint32_t s0 = smem_u32(sm);
    int tid = threadIdx.x, wid = tid >> 5, lid = tid & 31;
    int tile = blockIdx.x;            // 0..799
    int b = tile / 200;
    int px0 = (tile % 200) * 128;

    const float4* dp = (const float4*)g_dh;
    int l15 = lid & 15, l16 = (lid >> 4) * 8;

    float acc[4][4];
    #pragma unroll
    for (int j = 0; j < 4; j++)
        #pragma unroll
        for (int q = 0; q < 4; q++) acc[j][q] = 0.f;

    int g4 = tid & 15, pxl = tid >> 4;

    for (int tap = 0; tap < 9; tap++) {
        int th = tap / 3 - 1, tw = tap % 3 - 1;
        // ---- shift gather -> A hi/lo ----
        #pragma unroll 2
        for (int it = 0; it < 8; it++) {
            int px = pxl + it * 16;
            int pg = px0 + px;
            int h = pg / WW, w = pg - h * WW;
            int y = h + th, x = w + tw;
            float4 v = make_float4(0.f, 0.f, 0.f, 0.f);
            if (y >= 0 && y < HH && x >= 0 && x < WW)
                v = dp[((size_t)((b*HH + y)*WW + x)) * 16 + g4];
            __nv_bfloat162 h01 = __floats2bfloat162_rn(v.x, v.y);
            __nv_bfloat162 h23 = __floats2bfloat162_rn(v.z, v.w);
            __nv_bfloat162 l01 = __floats2bfloat162_rn(
                v.x - __bfloat162float(h01.x), v.y - __bfloat162float(h01.y));
            __nv_bfloat162 l23 = __floats2bfloat162_rn(
                v.z - __bfloat162float(h23.x), v.w - __bfloat162float(h23.y));
            uint32_t sw = sw128(px * 128 + g4 * 8);
            uint2 hv, lv;
            hv.x = *(uint32_t*)&h01; hv.y = *(uint32_t*)&h23;
            lv.x = *(uint32_t*)&l01; lv.y = *(uint32_t*)&l23;
            *(uint2*)(sm + OSM_A_HI + sw) = hv;
            *(uint2*)(sm + OSM_A_LO + sw) = lv;
        }
        // ---- B tile: [64 cin][64pad couts] (only 0..31 read) ----
        {
            const uint4* wh = (const uint4*)g_obh + tap * 512;
            const uint4* wl = (const uint4*)g_obl + tap * 512;
            #pragma unroll
            for (int i = tid; i < 512; i += 256) {
                int row = i >> 3, gq = i & 7;
                uint32_t sw = sw128(row * 128 + gq * 16);
                *(uint4*)(sm + OSM_B_HI + sw) = wh[i];
                *(uint4*)(sm + OSM_B_LO + sw) = wl[i];
            }
        }
        __syncthreads();

        // ---- MMA: warp wid -> px rows 16wid..+15, couts 0..31 ----
        #pragma unroll
        for (int ks = 0; ks < 4; ks++) {
            int k0 = ks * 16;
            uint32_t sa = sw128((wid*16 + l15) * 128 + (k0 + l16) * 2);
            uint32_t ah[4], al[4];
            ldsm_x4(ah[0], ah[1], ah[2], ah[3], s0 + OSM_A_HI + sa);
            ldsm_x4(al[0], al[1], al[2], al[3], s0 + OSM_A_LO + sa);
            #pragma unroll
            for (int jj = 0; jj < 2; jj++) {
                uint32_t sb = sw128((k0 + l15) * 128 + (jj*16 + l16) * 2);
                uint32_t bh0, bh1, bh2, bh3, bl0, bl1, bl2, bl3;
                ldsm_x4t(bh0, bh1, bh2, bh3, s0 + OSM_B_HI + sb);
                ldsm_x4t(bl0, bl1, bl2, bl3, s0 + OSM_B_LO + sb);
                mma16816(acc[2*jj],   ah, bh0, bh1);
                mma16816(acc[2*jj],   ah, bl0, bl1);
                mma16816(acc[2*jj],   al, bh0, bh1);
                mma16816(acc[2*jj+1], ah, bh2, bh3);
                mma16816(acc[2*jj+1], ah, bl2, bl3);
                mma16816(acc[2*jj+1], al, bh2, bh3);
            }
        }
        __syncthreads();
    }

    // ---- epilogue: clamp + write offsets (NCHW [B,18,H,W]) ----
    {
        int prow = wid * 16 + (lid >> 2);
        int pg0 = px0 + prow, pg1 = pg0 + 8;
        #pragma unroll
        for (int j = 0; j < 4; j++) {
            int c0 = j * 8 + (lid & 3) * 2;
            if (c0 < 18) {
                float v0 = fminf(1.f, fmaxf(-1.f, acc[j][0]));
                float v2 = fminf(1.f, fmaxf(-1.f, acc[j][2]));
                int i0 = (b*18 + c0)*HW + pg0;
                int i1 = (b*18 + c0)*HW + pg1;
                g_off[i0] = v0; g_off[i1] = v2;
                if (outoff) { outoff[i0] = v0; outoff[i1] = v2; }
                if (c0 + 1 < 18) {
                    float v1 = fminf(1.f, fmaxf(-1.f, acc[j][1]));
                    float v3 = fminf(1.f, fmaxf(-1.f, acc[j][3]));
                    g_off[i0 + HW] = v1; g_off[i1 + HW] = v3;
                    if (outoff) { outoff[i0 + HW] = v1; outoff[i1 + HW] = v3; }
                }
            }
        }
    }
}

// ---------------------------------------------------------------------------
// Main deformable conv with warp-level bf16 HMMA (unchanged from R4)
// ---------------------------------------------------------------------------
#define SM_A_HI 0
#define SM_A_LO 16384
#define SM_B_HI 32768
#define SM_B_LO 40960
#define SM_PBW  49152
#define SM_SIZE (53248 + 1024)

__global__ __launch_bounds__(256, 3) void k_deform(float* __restrict__ out) {
    extern __shared__ char smraw[];
    char* sm = (char*)(((uintptr_t)smraw + 1023) & ~(uintptr_t)1023);
    uint32_t s0 = smem_u32(sm);
    int tid = threadIdx.x, wid = tid >> 5, lid = tid & 31;
    int tile = blockIdx.x;            // 0..799
    int b = tile / 200;
    int px0 = (tile % 200) * 128;

    int2* sBW = (int2*)(sm + SM_PBW);
    const float4* xp = (const float4*)g_xh;

    int mw = wid & 3, nw = wid >> 2;
    int l15 = lid & 15, l16 = (lid >> 4) * 8;

    float acc[2][4][4];
    #pragma unroll
    for (int mt = 0; mt < 2; mt++)
        #pragma unroll
        for (int j = 0; j < 4; j++)
            #pragma unroll
            for (int q = 0; q < 4; q++) acc[mt][j][q] = 0.f;

    for (int tap = 0; tap < 9; tap++) {
        {
            int px = tid >> 1;
            int pg = px0 + px;
            int h = pg / WW, w = pg % WW;
            float dy = g_off[(b*18 + 2*tap    )*HW + pg];
            float dx = g_off[(b*18 + 2*tap + 1)*HW + pg];
            float py = (float)h - 1.f + (float)(tap / 3) + dy;
            float pxx = (float)w - 1.f + (float)(tap % 3) + dx;
            float y0f = floorf(py), x0f = floorf(pxx);
            float fy = py - y0f, fx = pxx - x0f;
            int y0 = (int)y0f, x0 = (int)x0f;
            #pragma unroll
            for (int j = 0; j < 2; j++) {
                int cn = (tid & 1) * 2 + j;
                int yy = y0 + (cn >> 1), xx = x0 + (cn & 1);
                float wt = ((cn >> 1) ? fy : 1.f - fy) * ((cn & 1) ? fx : 1.f - fx);
                bool valid = (yy >= 0) && (yy < HH) && (xx >= 0) && (xx < WW);
                int yc = min(max(yy, 0), HH - 1), xc = min(max(xx, 0), WW - 1);
                sBW[cn*128 + px] = make_int2(((b*HH + yc)*WW + xc) * CC,
                                             __float_as_int(valid ? wt : 0.f));
            }
        }
        __syncthreads();

        {
            int g4 = tid & 15;
            #pragma unroll 2
            for (int it = 0; it < 8; it++) {
                int px = (tid >> 4) + it * 16;
                int2 q0 = sBW[px],       q1 = sBW[128 + px];
                int2 q2 = sBW[256 + px], q3 = sBW[384 + px];
                float w0 = __int_as_float(q0.y), w1 = __int_as_float(q1.y);
                float w2 = __int_as_float(q2.y), w3 = __int_as_float(q3.y);
                float4 a0 = xp[(q0.x >> 2) + g4];
                float4 a1 = xp[(q1.x >> 2) + g4];
                float4 a2 = xp[(q2.x >> 2) + g4];
                float4 a3 = xp[(q3.x >> 2) + g4];
                float4 v;
                v.x = w0*a0.x + w1*a1.x + w2*a2.x + w3*a3.x;
                v.y = w0*a0.y + w1*a1.y + w2*a2.y + w3*a3.y;
                v.z = w0*a0.z + w1*a1.z + w2*a2.z + w3*a3.z;
                v.w = w0*a0.w + w1*a1.w + w2*a2.w + w3*a3.w;
                __nv_bfloat162 h01 = __floats2bfloat162_rn(v.x, v.y);
                __nv_bfloat162 h23 = __floats2bfloat162_rn(v.z, v.w);
                __nv_bfloat162 l01 = __floats2bfloat162_rn(
                    v.x - __bfloat162float(h01.x), v.y - __bfloat162float(h01.y));
                __nv_bfloat162 l23 = __floats2bfloat162_rn(
                    v.z - __bfloat162float(h23.x), v.w - __bfloat162float(h23.y));
                uint32_t sw = sw128(px * 128 + g4 * 8);
                uint2 hv, lv;
                hv.x = *(uint32_t*)&h01; hv.y = *(uint32_t*)&h23;
                lv.x = *(uint32_t*)&l01; lv.y = *(uint32_t*)&l23;
                *(uint2*)(sm + SM_A_HI + sw) = hv;
                *(uint2*)(sm + SM_A_LO + sw) = lv;
            }
        }

        {
            const uint4* wh = (const uint4*)g_wbh + tap * 512;
            const uint4* wl = (const uint4*)g_wbl + tap * 512;
            #pragma unroll
            for (int i = tid; i < 512; i += 256) {
                int row = i >> 3, gq = i & 7;
                uint32_t sw = sw128(row * 128 + gq * 16);
                *(uint4*)(sm + SM_B_HI + sw) = wh[i];
                *(uint4*)(sm + SM_B_LO + sw) = wl[i];
            }
        }
        __syncthreads();

        #pragma unroll
        for (int ks = 0; ks < 4; ks++) {
            int k0 = ks * 16;
            uint32_t ah[2][4], al[2][4];
            #pragma unroll
            for (int mt = 0; mt < 2; mt++) {
                uint32_t sa = sw128((mw*32 + mt*16 + l15) * 128 + (k0 + l16) * 2);
                ldsm_x4(ah[mt][0], ah[mt][1], ah[mt][2], ah[mt][3], s0 + SM_A_HI + sa);
                ldsm_x4(al[mt][0], al[mt][1], al[mt][2], al[mt][3], s0 + SM_A_LO + sa);
            }
            #pragma unroll
            for (int jj = 0; jj < 2; jj++) {
                uint32_t sb = sw128((k0 + l15) * 128 + (nw*32 + jj*16 + l16) * 2);
                uint32_t bh0, bh1, bh2, bh3, bl0, bl1, bl2, bl3;
                ldsm_x4t(bh0, bh1, bh2, bh3, s0 + SM_B_HI + sb);
                ldsm_x4t(bl0, bl1, bl2, bl3, s0 + SM_B_LO + sb);
                #pragma unroll
                for (int mt = 0; mt < 2; mt++) {
                    mma16816(acc[mt][2*jj],   ah[mt], bh0, bh1);
                    mma16816(acc[mt][2*jj],   ah[mt], bl0, bl1);
                    mma16816(acc[mt][2*jj],   al[mt], bh0, bh1);
                    mma16816(acc[mt][2*jj+1], ah[mt], bh2, bh3);
                    mma16816(acc[mt][2*jj+1], ah[mt], bl2, bl3);
                    mma16816(acc[mt][2*jj+1], al[mt], bh2, bh3);
                }
            }
        }
        __syncthreads();
    }

    {
        float* op = out + (size_t)b * COUT * HW;
        #pragma unroll
        for (int mt = 0; mt < 2; mt++) {
            int prow = px0 + mw*32 + mt*16 + (lid >> 2);
            #pragma unroll
            for (int j = 0; j < 4; j++) {
                int c0 = nw*32 + j*8 + (lid & 3) * 2;
                op[(c0    ) * HW + prow    ] = acc[mt][j][0];
                op[(c0 + 1) * HW + prow    ] = acc[mt][j][1];
                op[(c0    ) * HW + prow + 8] = acc[mt][j][2];
                op[(c0 + 1) * HW + prow + 8] = acc[mt][j][3];
            }
        }
    }
}

// ---------------------------------------------------------------------------
// BN stats + apply
// ---------------------------------------------------------------------------
__global__ void k_stats(const float* __restrict__ out) {
    int c = blockIdx.x, bi = blockIdx.y;
    float s = 0.f, sq = 0.f;
    for (int n = bi * 256 + threadIdx.x; n < BB * HW / 4; n += gridDim.y * 256) {
        int b = n / (HW/4), i = n - b * (HW/4);
        float4 v = ((const float4*)(out + (b * COUT + c) * HW))[i];
        s  += v.x + v.y + v.z + v.w;
        sq += v.x*v.x + v.y*v.y + v.z*v.z + v.w*v.w;
    }
    __shared__ float rs[256], rq[256];
    rs[threadIdx.x] = s; rq[threadIdx.x] = sq;
    __syncthreads();
    for (int st = 128; st > 0; st >>= 1) {
        if (threadIdx.x < st) {
            rs[threadIdx.x] += rs[threadIdx.x + st];
            rq[threadIdx.x] += rq[threadIdx.x + st];
        }
        __syncthreads();
    }
    if (threadIdx.x == 0) {
        g_part[(c * 16 + bi) * 2]     = rs[0];
        g_part[(c * 16 + bi) * 2 + 1] = rq[0];
    }
}

__global__ void k_finalize(const float* __restrict__ gamma,
                           const float* __restrict__ beta) {
    int c = threadIdx.x;
    if (c < COUT) {
        float s = 0.f, sq = 0.f;
        for (int i = 0; i < 16; i++) {
            s  += g_part[(c * 16 + i) * 2];
            sq += g_part[(c * 16 + i) * 2 + 1];
        }
        float inv_n = 1.f / (float)(BB * HW);
        float mean = s * inv_n;
        float var  = sq * inv_n - mean * mean;
        float sc = gamma[c] * rsqrtf(var + EPSV);
        g_scale[c] = sc;
        g_shift[c] = beta[c] - mean * sc;
    }
}

__global__ void k_bnrelu(float* __restrict__ out) {
    int idx = blockIdx.x * 256 + threadIdx.x;
    int c = (idx / (HW / 4)) & 63;
    float sc = g_scale[c], sh = g_shift[c];
    float4 v = ((float4*)out)[idx];
    v.x = fmaxf(0.f, v.x * sc + sh);
    v.y = fmaxf(0.f, v.y * sc + sh);
    v.z = fmaxf(0.f, v.z * sc + sh);
    v.w = fmaxf(0.f, v.w * sc + sh);
    ((float4*)out)[idx] = v;
}

// ---------------------------------------------------------------------------
extern "C" void kernel_launch(void* const* d_in, const int* in_sizes, int n_in,
                              void* d_out, int out_size) {
    const float* x     = (const float*)d_in[0];
    const float* d     = (const float*)d_in[1];
    const float* ow    = (const float*)d_in[2];
    const float* cw    = (const float*)d_in[3];
    const float* gamma = (const float*)d_in[4];
    const float* beta  = (const float*)d_in[5];
    float* out = (float*)d_out;
    float* outoff = (out_size >= OUT_MAIN + OUT_OFF) ? (out + OUT_MAIN) : nullptr;

    cudaFuncSetAttribute(k_deform, cudaFuncAttributeMaxDynamicSharedMemorySize,
                         SM_SIZE);
    cudaFuncSetAttribute(k_offmma, cudaFuncAttributeMaxDynamicSharedMemorySize,
                         OSM_SIZE);

    k_transpose<<<dim3(10, BB * HH, 2), dim3(32, 8)>>>(x, d);
    k_wsplit<<<(K2 * CC * COUT + 255) / 256, 256>>>(cw);
    k_owsplit<<<(K2 * OFFC * 64 + 255) / 256, 256>>>(ow);
    k_offmma<<<800, 256, OSM_SIZE>>>(outoff);
    k_deform<<<800, 256, SM_SIZE>>>(out);
    k_stats<<<dim3(COUT, 16), 256>>>(out);
    k_finalize<<<1, 64>>>(gamma, beta);
    k_bnrelu<<<OUT_MAIN / 4 / 256, 256>>>(out);
}

// round 7
// speedup vs baseline: 3.8167x; 1.0245x over previous
#include <cuda_runtime.h>
#include <cuda_bf16.h>
#include <cstdint>

#define HH 160
#define WW 160
#define BB 4
#define CC 64
#define COUT 64
#define OFFC 64
#define K2 9
#define HW (HH*WW)             // 25600
#define OUT_MAIN (BB*COUT*HW)  // 6553600
#define OUT_OFF  (BB*2*K2*HW)  // 1843200
#define EPSV 1e-5f

// ---- warp-MMA helpers (plain PTX, works on .target sm_103) ----------------
__device__ __forceinline__ uint32_t smem_u32(const void* p) {
    uint32_t a;
    asm("{ .reg .u64 t; cvta.to.shared.u64 t, %1; cvt.u32.u64 %0, t; }"
        : "=r"(a) : "l"(p));
    return a;
}
__device__ __forceinline__ void ldsm_x4(uint32_t& r0, uint32_t& r1,
                                        uint32_t& r2, uint32_t& r3, uint32_t a) {
    asm volatile("ldmatrix.sync.aligned.m8n8.x4.shared.b16 {%0,%1,%2,%3}, [%4];"
                 : "=r"(r0), "=r"(r1), "=r"(r2), "=r"(r3) : "r"(a));
}
__device__ __forceinline__ void ldsm_x4t(uint32_t& r0, uint32_t& r1,
                                         uint32_t& r2, uint32_t& r3, uint32_t a) {
    asm volatile("ldmatrix.sync.aligned.m8n8.x4.trans.shared.b16 {%0,%1,%2,%3}, [%4];"
                 : "=r"(r0), "=r"(r1), "=r"(r2), "=r"(r3) : "r"(a));
}
__device__ __forceinline__ void mma16816(float* c, const uint32_t* a,
                                         uint32_t b0, uint32_t b1) {
    asm volatile("mma.sync.aligned.m16n8k16.row.col.f32.bf16.bf16.f32 "
                 "{%0,%1,%2,%3}, {%4,%5,%6,%7}, {%8,%9}, {%0,%1,%2,%3};"
                 : "+f"(c[0]), "+f"(c[1]), "+f"(c[2]), "+f"(c[3])
                 : "r"(a[0]), "r"(a[1]), "r"(a[2]), "r"(a[3]), "r"(b0), "r"(b1));
}
__device__ __forceinline__ uint32_t sw128(uint32_t off) {
    return off ^ ((off >> 3) & 0x70);
}
__device__ __forceinline__ uint32_t sw64(uint32_t off) {
    return off ^ ((off >> 3) & 0x30);
}

// ---- global scratch -------------------------------------------------------
__device__ float g_xh[BB*HW*CC];                 // x in NHWC fp32
__device__ float g_dh[BB*HW*CC];                 // d in NHWC fp32
__device__ __nv_bfloat16 g_wbh[K2*CC*COUT];      // conv W hi [tap][cin][cout]
__device__ __nv_bfloat16 g_wbl[K2*CC*COUT];      // conv W lo
__device__ __nv_bfloat16 g_obh[K2*OFFC*32];      // offset W hi [tap][cin][32pad]
__device__ __nv_bfloat16 g_obl[K2*OFFC*32];      // offset W lo
__device__ float g_off[BB*2*K2*HW];              // clamped offsets NCHW
__device__ float g_part[COUT*16*2];
__device__ float g_scale[COUT];
__device__ float g_shift[COUT];

// ---------------------------------------------------------------------------
// NCHW -> NHWC transpose of x (z=0) and d (z=1)
// ---------------------------------------------------------------------------
__global__ void k_transpose(const float* __restrict__ x,
                            const float* __restrict__ d) {
    __shared__ float tile[32][33];
    const float* src = blockIdx.z ? d : x;
    float* dst = blockIdx.z ? g_dh : g_xh;
    int bh = blockIdx.y;
    int b = bh / HH, h = bh % HH;
    int tw = blockIdx.x % 5, tc = blockIdx.x / 5;
    int w = tw * 32 + threadIdx.x;
    #pragma unroll
    for (int i = 0; i < 4; i++) {
        int cl = threadIdx.y + i * 8;
        tile[cl][threadIdx.x] = src[((b*CC + tc*32 + cl)*HH + h)*WW + w];
    }
    __syncthreads();
    #pragma unroll
    for (int i = 0; i < 4; i++) {
        int wl = threadIdx.y + i * 8;
        dst[((b*HH + h)*WW + tw*32 + wl)*CC + tc*32 + threadIdx.x]
            = tile[threadIdx.x][wl];
    }
}

// ---------------------------------------------------------------------------
// Split conv_w into bf16 hi/lo, [tap][cin][cout]
// ---------------------------------------------------------------------------
__global__ void k_wsplit(const float* __restrict__ cw) {
    int i = blockIdx.x * 256 + threadIdx.x;      // K2*CC*COUT = 36864
    if (i < K2*CC*COUT) {
        int tap = i / (CC*COUT), ci = (i / COUT) % CC, co = i % COUT;
        float w = cw[(co*CC + ci)*K2 + tap];
        __nv_bfloat16 h = __float2bfloat16(w);
        float lo = w - __bfloat162float(h);
        g_wbh[i] = h;
        g_wbl[i] = __float2bfloat16(lo);
    }
}

// ---------------------------------------------------------------------------
// Split offset_w into bf16 hi/lo, [tap][cin][32pad] (couts 18..31 zero)
// ---------------------------------------------------------------------------
__global__ void k_owsplit(const float* __restrict__ ow) {
    int i = blockIdx.x * 256 + threadIdx.x;      // K2*OFFC*32 = 18432
    if (i < K2*OFFC*32) {
        int tap = i / (OFFC*32), ci = (i / 32) % OFFC, co = i % 32;
        float w = 0.f;
        if (co < 18) w = ow[(co*OFFC + ci)*K2 + tap];
        __nv_bfloat16 h = __float2bfloat16(w);
        float lo = w - __bfloat162float(h);
        g_obh[i] = h;
        g_obl[i] = __float2bfloat16(lo);
    }
}

// ---------------------------------------------------------------------------
// Offset conv as HMMA GEMM: 256-px tiles, [256px x 576] x [576 x 32(pad18)].
// Warp = M32 x N32 (8 warps). B stored 32-wide, 64B rows, SW64 swizzle.
// ---------------------------------------------------------------------------
#define OSM_A_HI 0
#define OSM_A_LO 32768
#define OSM_B_HI 65536
#define OSM_B_LO 69632
#define OSM_SIZE (73728 + 1024)

__global__ __launch_bounds__(256, 3) void k_offmma(float* __restrict__ outoff) {
    extern __shared__ char smraw[];
    char* sm = (char*)(((uintptr_t)smraw + 1023) & ~(uintptr_t)1023);
    uint32_t s0 = smem_u32(sm);
    int tid = threadIdx.x, wid = tid >> 5, lid = tid & 31;
    int tile = blockIdx.x;            // 0..399
    int b = tile / 100;
    int px0 = (tile % 100) * 256;

    const float4* dp = (const float4*)g_dh;
    int l15 = lid & 15, l16 = (lid >> 4) * 8;
    int g4 = tid & 15, pxl = tid >> 4;

    float acc[2][4][4];
    #pragma unroll
    for (int mt = 0; mt < 2; mt++)
        #pragma unroll
        for (int j = 0; j < 4; j++)
            #pragma unroll
            for (int q = 0; q < 4; q++) acc[mt][j][q] = 0.f;

    for (int tap = 0; tap < 9; tap++) {
        int th = tap / 3 - 1, tw = tap % 3 - 1;
        // ---- shift gather -> A hi/lo (SW128, 256 rows) ----
        #pragma unroll 2
        for (int it = 0; it < 16; it++) {
            int px = pxl + it * 16;
            int pg = px0 + px;
            int h = pg / WW, w = pg - h * WW;
            int y = h + th, x = w + tw;
            float4 v = make_float4(0.f, 0.f, 0.f, 0.f);
            if (y >= 0 && y < HH && x >= 0 && x < WW)
                v = dp[((size_t)((b*HH + y)*WW + x)) * 16 + g4];
            __nv_bfloat162 h01 = __floats2bfloat162_rn(v.x, v.y);
            __nv_bfloat162 h23 = __floats2bfloat162_rn(v.z, v.w);
            __nv_bfloat162 l01 = __floats2bfloat162_rn(
                v.x - __bfloat162float(h01.x), v.y - __bfloat162float(h01.y));
            __nv_bfloat162 l23 = __floats2bfloat162_rn(
                v.z - __bfloat162float(h23.x), v.w - __bfloat162float(h23.y));
            uint32_t sw = sw128(px * 128 + g4 * 8);
            uint2 hv, lv;
            hv.x = *(uint32_t*)&h01; hv.y = *(uint32_t*)&h23;
            lv.x = *(uint32_t*)&l01; lv.y = *(uint32_t*)&l23;
            *(uint2*)(sm + OSM_A_HI + sw) = hv;
            *(uint2*)(sm + OSM_A_LO + sw) = lv;
        }
        // ---- B tile: [64 cin][32 couts], 64B rows, SW64 ----
        {
            const uint4* wh = (const uint4*)g_obh + tap * 256;
            const uint4* wl = (const uint4*)g_obl + tap * 256;
            int row = tid >> 2, q = tid & 3;           // 256 threads = 256 uint4
            uint32_t sw = sw64(row * 64 + q * 16);
            *(uint4*)(sm + OSM_B_HI + sw) = wh[tid];
            *(uint4*)(sm + OSM_B_LO + sw) = wl[tid];
        }
        __syncthreads();

        // ---- MMA: warp wid -> px rows 32wid..+31, couts 0..31 ----
        #pragma unroll
        for (int ks = 0; ks < 4; ks++) {
            int k0 = ks * 16;
            uint32_t ah[2][4], al[2][4];
            #pragma unroll
            for (int mt = 0; mt < 2; mt++) {
                uint32_t sa = sw128((wid*32 + mt*16 + l15) * 128 + (k0 + l16) * 2);
                ldsm_x4(ah[mt][0], ah[mt][1], ah[mt][2], ah[mt][3], s0 + OSM_A_HI + sa);
                ldsm_x4(al[mt][0], al[mt][1], al[mt][2], al[mt][3], s0 + OSM_A_LO + sa);
            }
            #pragma unroll
            for (int jj = 0; jj < 2; jj++) {
                uint32_t sb = sw64((k0 + l15) * 64 + (jj*16 + l16) * 2);
                uint32_t bh0, bh1, bh2, bh3, bl0, bl1, bl2, bl3;
                ldsm_x4t(bh0, bh1, bh2, bh3, s0 + OSM_B_HI + sb);
                ldsm_x4t(bl0, bl1, bl2, bl3, s0 + OSM_B_LO + sb);
                #pragma unroll
                for (int mt = 0; mt < 2; mt++) {
                    mma16816(acc[mt][2*jj],   ah[mt], bh0, bh1);
                    mma16816(acc[mt][2*jj],   ah[mt], bl0, bl1);
                    mma16816(acc[mt][2*jj],   al[mt], bh0, bh1);
                    mma16816(acc[mt][2*jj+1], ah[mt], bh2, bh3);
                    mma16816(acc[mt][2*jj+1], ah[mt], bl2, bl3);
                    mma16816(acc[mt][2*jj+1], al[mt], bh2, bh3);
                }
            }
        }
        __syncthreads();
    }

    // ---- epilogue: clamp + write offsets (NCHW [B,18,H,W]) ----
    #pragma unroll
    for (int mt = 0; mt < 2; mt++) {
        int prow = wid * 32 + mt * 16 + (lid >> 2);
        int pg0 = px0 + prow, pg1 = pg0 + 8;
        #pragma unroll
        for (int j = 0; j < 4; j++) {
            int c0 = j * 8 + (lid & 3) * 2;
            if (c0 < 18) {
                float v0 = fminf(1.f, fmaxf(-1.f, acc[mt][j][0]));
                float v2 = fminf(1.f, fmaxf(-1.f, acc[mt][j][2]));
                int i0 = (b*18 + c0)*HW + pg0;
                int i1 = (b*18 + c0)*HW + pg1;
                g_off[i0] = v0; g_off[i1] = v2;
                if (outoff) { outoff[i0] = v0; outoff[i1] = v2; }
                if (c0 + 1 < 18) {
                    float v1 = fminf(1.f, fmaxf(-1.f, acc[mt][j][1]));
                    float v3 = fminf(1.f, fmaxf(-1.f, acc[mt][j][3]));
                    g_off[i0 + HW] = v1; g_off[i1 + HW] = v3;
                    if (outoff) { outoff[i0 + HW] = v1; outoff[i1 + HW] = v3; }
                }
            }
        }
    }
}

// ---------------------------------------------------------------------------
// Main deformable conv with warp-level bf16 HMMA.
// R6 change: __launch_bounds__(256,4) -> 64 regs, 4 CTAs/SM.
// ---------------------------------------------------------------------------
#define SM_A_HI 0
#define SM_A_LO 16384
#define SM_B_HI 32768
#define SM_B_LO 40960
#define SM_PBW  49152
#define SM_SIZE (53248 + 1024)

__global__ __launch_bounds__(256, 4) void k_deform(float* __restrict__ out) {
    extern __shared__ char smraw[];
    char* sm = (char*)(((uintptr_t)smraw + 1023) & ~(uintptr_t)1023);
    uint32_t s0 = smem_u32(sm);
    int tid = threadIdx.x, wid = tid >> 5, lid = tid & 31;
    int tile = blockIdx.x;            // 0..799
    int b = tile / 200;
    int px0 = (tile % 200) * 128;

    int2* sBW = (int2*)(sm + SM_PBW);
    const float4* xp = (const float4*)g_xh;

    int mw = wid & 3, nw = wid >> 2;
    int l15 = lid & 15, l16 = (lid >> 4) * 8;

    float acc[2][4][4];
    #pragma unroll
    for (int mt = 0; mt < 2; mt++)
        #pragma unroll
        for (int j = 0; j < 4; j++)
            #pragma unroll
            for (int q = 0; q < 4; q++) acc[mt][j][q] = 0.f;

    for (int tap = 0; tap < 9; tap++) {
        {
            int px = tid >> 1;
            int pg = px0 + px;
            int h = pg / WW, w = pg % WW;
            float dy = g_off[(b*18 + 2*tap    )*HW + pg];
            float dx = g_off[(b*18 + 2*tap + 1)*HW + pg];
            float py = (float)h - 1.f + (float)(tap / 3) + dy;
            float pxx = (float)w - 1.f + (float)(tap % 3) + dx;
            float y0f = floorf(py), x0f = floorf(pxx);
            float fy = py - y0f, fx = pxx - x0f;
            int y0 = (int)y0f, x0 = (int)x0f;
            #pragma unroll
            for (int j = 0; j < 2; j++) {
                int cn = (tid & 1) * 2 + j;
                int yy = y0 + (cn >> 1), xx = x0 + (cn & 1);
                float wt = ((cn >> 1) ? fy : 1.f - fy) * ((cn & 1) ? fx : 1.f - fx);
                bool valid = (yy >= 0) && (yy < HH) && (xx >= 0) && (xx < WW);
                int yc = min(max(yy, 0), HH - 1), xc = min(max(xx, 0), WW - 1);
                sBW[cn*128 + px] = make_int2(((b*HH + yc)*WW + xc) * CC,
                                             __float_as_int(valid ? wt : 0.f));
            }
        }
        __syncthreads();

        {
            int g4 = tid & 15;
            #pragma unroll 2
            for (int it = 0; it < 8; it++) {
                int px = (tid >> 4) + it * 16;
                int2 q0 = sBW[px],       q1 = sBW[128 + px];
                int2 q2 = sBW[256 + px], q3 = sBW[384 + px];
                float w0 = __int_as_float(q0.y), w1 = __int_as_float(q1.y);
                float w2 = __int_as_float(q2.y), w3 = __int_as_float(q3.y);
                float4 a0 = xp[(q0.x >> 2) + g4];
                float4 a1 = xp[(q1.x >> 2) + g4];
                float4 a2 = xp[(q2.x >> 2) + g4];
                float4 a3 = xp[(q3.x >> 2) + g4];
                float4 v;
                v.x = w0*a0.x + w1*a1.x + w2*a2.x + w3*a3.x;
                v.y = w0*a0.y + w1*a1.y + w2*a2.y + w3*a3.y;
                v.z = w0*a0.z + w1*a1.z + w2*a2.z + w3*a3.z;
                v.w = w0*a0.w + w1*a1.w + w2*a2.w + w3*a3.w;
                __nv_bfloat162 h01 = __floats2bfloat162_rn(v.x, v.y);
                __nv_bfloat162 h23 = __floats2bfloat162_rn(v.z, v.w);
                __nv_bfloat162 l01 = __floats2bfloat162_rn(
                    v.x - __bfloat162float(h01.x), v.y - __bfloat162float(h01.y));
                __nv_bfloat162 l23 = __floats2bfloat162_rn(
                    v.z - __bfloat162float(h23.x), v.w - __bfloat162float(h23.y));
                uint32_t sw = sw128(px * 128 + g4 * 8);
                uint2 hv, lv;
                hv.x = *(uint32_t*)&h01; hv.y = *(uint32_t*)&h23;
                lv.x = *(uint32_t*)&l01; lv.y = *(uint32_t*)&l23;
                *(uint2*)(sm + SM_A_HI + sw) = hv;
                *(uint2*)(sm + SM_A_LO + sw) = lv;
            }
        }

        {
            const uint4* wh = (const uint4*)g_wbh + tap * 512;
            const uint4* wl = (const uint4*)g_wbl + tap * 512;
            #pragma unroll
            for (int i = tid; i < 512; i += 256) {
                int row = i >> 3, gq = i & 7;
                uint32_t sw = sw128(row * 128 + gq * 16);
                *(uint4*)(sm + SM_B_HI + sw) = wh[i];
                *(uint4*)(sm + SM_B_LO + sw) = wl[i];
            }
        }
        __syncthreads();

        #pragma unroll
        for (int ks = 0; ks < 4; ks++) {
            int k0 = ks * 16;
            uint32_t ah[2][4], al[2][4];
            #pragma unroll
            for (int mt = 0; mt < 2; mt++) {
                uint32_t sa = sw128((mw*32 + mt*16 + l15) * 128 + (k0 + l16) * 2);
                ldsm_x4(ah[mt][0], ah[mt][1], ah[mt][2], ah[mt][3], s0 + SM_A_HI + sa);
                ldsm_x4(al[mt][0], al[mt][1], al[mt][2], al[mt][3], s0 + SM_A_LO + sa);
            }
            #pragma unroll
            for (int jj = 0; jj < 2; jj++) {
                uint32_t sb = sw128((k0 + l15) * 128 + (nw*32 + jj*16 + l16) * 2);
                uint32_t bh0, bh1, bh2, bh3, bl0, bl1, bl2, bl3;
                ldsm_x4t(bh0, bh1, bh2, bh3, s0 + SM_B_HI + sb);
                ldsm_x4t(bl0, bl1, bl2, bl3, s0 + SM_B_LO + sb);
                #pragma unroll
                for (int mt = 0; mt < 2; mt++) {
                    mma16816(acc[mt][2*jj],   ah[mt], bh0, bh1);
                    mma16816(acc[mt][2*jj],   ah[mt], bl0, bl1);
                    mma16816(acc[mt][2*jj],   al[mt], bh0, bh1);
                    mma16816(acc[mt][2*jj+1], ah[mt], bh2, bh3);
                    mma16816(acc[mt][2*jj+1], ah[mt], bl2, bl3);
                    mma16816(acc[mt][2*jj+1], al[mt], bh2, bh3);
                }
            }
        }
        __syncthreads();
    }

    {
        float* op = out + (size_t)b * COUT * HW;
        #pragma unroll
        for (int mt = 0; mt < 2; mt++) {
            int prow = px0 + mw*32 + mt*16 + (lid >> 2);
            #pragma unroll
            for (int j = 0; j < 4; j++) {
                int c0 = nw*32 + j*8 + (lid & 3) * 2;
                op[(c0    ) * HW + prow    ] = acc[mt][j][0];
                op[(c0 + 1) * HW + prow    ] = acc[mt][j][1];
                op[(c0    ) * HW + prow + 8] = acc[mt][j][2];
                op[(c0 + 1) * HW + prow + 8] = acc[mt][j][3];
            }
        }
    }
}

// ---------------------------------------------------------------------------
// BN stats + apply
// ---------------------------------------------------------------------------
__global__ void k_stats(const float* __restrict__ out) {
    int c = blockIdx.x, bi = blockIdx.y;
    float s = 0.f, sq = 0.f;
    for (int n = bi * 256 + threadIdx.x; n < BB * HW / 4; n += gridDim.y * 256) {
        int b = n / (HW/4), i = n - b * (HW/4);
        float4 v = ((const float4*)(out + (b * COUT + c) * HW))[i];
        s  += v.x + v.y + v.z + v.w;
        sq += v.x*v.x + v.y*v.y + v.z*v.z + v.w*v.w;
    }
    __shared__ float rs[256], rq[256];
    rs[threadIdx.x] = s; rq[threadIdx.x] = sq;
    __syncthreads();
    for (int st = 128; st > 0; st >>= 1) {
        if (threadIdx.x < st) {
            rs[threadIdx.x] += rs[threadIdx.x + st];
            rq[threadIdx.x] += rq[threadIdx.x + st];
        }
        __syncthreads();
    }
    if (threadIdx.x == 0) {
        g_part[(c * 16 + bi) * 2]     = rs[0];
        g_part[(c * 16 + bi) * 2 + 1] = rq[0];
    }
}

__global__ void k_finalize(const float* __restrict__ gamma,
                           const float* __restrict__ beta) {
    int c = threadIdx.x;
    if (c < COUT) {
        float s = 0.f, sq = 0.f;
        for (int i = 0; i < 16; i++) {
            s  += g_part[(c * 16 + i) * 2];
            sq += g_part[(c * 16 + i) * 2 + 1];
        }
        float inv_n = 1.f / (float)(BB * HW);
        float mean = s * inv_n;
        float var  = sq * inv_n - mean * mean;
        float sc = gamma[c] * rsqrtf(var + EPSV);
        g_scale[c] = sc;
        g_shift[c] = beta[c] - mean * sc;
    }
}

__global__ void k_bnrelu(float* __restrict__ out) {
    int idx = blockIdx.x * 256 + threadIdx.x;
    int c = (idx / (HW / 4)) & 63;
    float sc = g_scale[c], sh = g_shift[c];
    float4 v = ((float4*)out)[idx];
    v.x = fmaxf(0.f, v.x * sc + sh);
    v.y = fmaxf(0.f, v.y * sc + sh);
    v.z = fmaxf(0.f, v.z * sc + sh);
    v.w = fmaxf(0.f, v.w * sc + sh);
    ((float4*)out)[idx] = v;
}

// ---------------------------------------------------------------------------
extern "C" void kernel_launch(void* const* d_in, const int* in_sizes, int n_in,
                              void* d_out, int out_size) {
    const float* x     = (const float*)d_in[0];
    const float* d     = (const float*)d_in[1];
    const float* ow    = (const float*)d_in[2];
    const float* cw    = (const float*)d_in[3];
    const float* gamma = (const float*)d_in[4];
    const float* beta  = (const float*)d_in[5];
    float* out = (float*)d_out;
    float* outoff = (out_size >= OUT_MAIN + OUT_OFF) ? (out + OUT_MAIN) : nullptr;

    cudaFuncSetAttribute(k_deform, cudaFuncAttributeMaxDynamicSharedMemorySize,
                         SM_SIZE);
    cudaFuncSetAttribute(k_offmma, cudaFuncAttributeMaxDynamicSharedMemorySize,
                         OSM_SIZE);

    k_transpose<<<dim3(10, BB * HH, 2), dim3(32, 8)>>>(x, d);
    k_wsplit<<<(K2 * CC * COUT + 255) / 256, 256>>>(cw);
    k_owsplit<<<(K2 * OFFC * 32 + 255) / 256, 256>>>(ow);
    k_offmma<<<400, 256, OSM_SIZE>>>(outoff);
    k_deform<<<800, 256, SM_SIZE>>>(out);
    k_stats<<<dim3(COUT, 16), 256>>>(out);
    k_finalize<<<1, 64>>>(gamma, beta);
    k_bnrelu<<<OUT_MAIN / 4 / 256, 256>>>(out);
}